// round 2
// baseline (speedup 1.0000x reference)
#include <cuda_runtime.h>
#include <math.h>

#define N_NODES 50000
#define N_EDGES 600000
#define N_GRAPHS 500
#define HID 128
#define N_LAYERS 3
#define N_CLASSES 10

// ---------------- scratch (device globals; no allocs allowed) ----------------
__device__ int   g_cnt[N_NODES];
__device__ int   g_row[N_NODES + 1];
__device__ int   g_tmp[N_NODES];
__device__ int   g_csr[N_EDGES];
__device__ float g_mean[(size_t)N_NODES * HID];
__device__ float g_h0[(size_t)N_NODES * HID];
__device__ float g_h1[(size_t)N_NODES * HID];
__device__ float g_pool[N_GRAPHS * HID];
__device__ float g_WlT[N_LAYERS * HID * HID];
__device__ float g_WrT[N_LAYERS * HID * HID];

// ---------------- tiny utility kernels ----------------
__global__ void zero_int_kernel(int* p, int n) {
    int i = blockIdx.x * blockDim.x + threadIdx.x;
    if (i < n) p[i] = 0;
}
__global__ void zero_float_kernel(float* p, int n) {
    int i = blockIdx.x * blockDim.x + threadIdx.x;
    if (i < n) p[i] = 0.0f;
}

__global__ void count_kernel(const int* __restrict__ dst, int* __restrict__ cnt, int nE) {
    int i = blockIdx.x * blockDim.x + threadIdx.x;
    if (i < nE) atomicAdd(&cnt[dst[i]], 1);
}

// single-block exclusive scan over N_NODES counts -> row_start[N_NODES+1]
__global__ void scan_kernel(const int* __restrict__ cnt, int* __restrict__ row) {
    __shared__ int part[1024];
    const int N = N_NODES;
    int t = threadIdx.x;
    int chunk = (N + 1023) / 1024;
    int beg = t * chunk;
    int end = min(beg + chunk, N);
    int s = 0;
    for (int i = beg; i < end; i++) s += cnt[i];
    part[t] = s;
    __syncthreads();
    // Hillis-Steele inclusive scan
    for (int off = 1; off < 1024; off <<= 1) {
        int v = part[t];
        int add = (t >= off) ? part[t - off] : 0;
        __syncthreads();
        part[t] = v + add;
        __syncthreads();
    }
    int run = (t == 0) ? 0 : part[t - 1];
    for (int i = beg; i < end; i++) { row[i] = run; run += cnt[i]; }
    if (t == 1023) row[N] = part[1023];
}

__global__ void copy_int_kernel(const int* __restrict__ src, int* __restrict__ dstp, int n) {
    int i = blockIdx.x * blockDim.x + threadIdx.x;
    if (i < n) dstp[i] = src[i];
}

__global__ void fill_csr_kernel(const int* __restrict__ src, const int* __restrict__ dst,
                                int* __restrict__ tmp, int* __restrict__ csr, int nE) {
    int i = blockIdx.x * blockDim.x + threadIdx.x;
    if (i < nE) {
        int p = atomicAdd(&tmp[dst[i]], 1);
        csr[p] = src[i];
    }
}

// transpose Wl/Wr (3 layers each, 128x128) so GEMM reads W coalesced: WT[k][j] = W[j][k]
__global__ void transpose_w_kernel(const float* __restrict__ Wl, const float* __restrict__ Wr,
                                   float* __restrict__ WlT, float* __restrict__ WrT) {
    int i = blockIdx.x * blockDim.x + threadIdx.x;
    if (i >= N_LAYERS * HID * HID) return;
    int l = i >> 14;
    int j = (i >> 7) & 127;
    int k = i & 127;
    int o = (l << 14) + (k << 7) + j;
    WlT[o] = Wl[i];
    WrT[o] = Wr[i];
}

// ---------------- mean aggregation: warp per node, CSR gather ----------------
__global__ void aggregate_kernel(const float* __restrict__ x, float* __restrict__ mean) {
    int w = (blockIdx.x * blockDim.x + threadIdx.x) >> 5;
    int lane = threadIdx.x & 31;
    if (w >= N_NODES) return;
    int beg = g_row[w];
    int end = g_row[w + 1];
    float4 s = make_float4(0.f, 0.f, 0.f, 0.f);
    for (int i = beg; i < end; i++) {
        int sn = g_csr[i];
        float4 v = *(const float4*)(x + (size_t)sn * HID + lane * 4);
        s.x += v.x; s.y += v.y; s.z += v.z; s.w += v.w;
    }
    float ic = 1.0f / fmaxf((float)(end - beg), 1.0f);
    s.x *= ic; s.y *= ic; s.z *= ic; s.w *= ic;
    *(float4*)(mean + (size_t)w * HID + lane * 4) = s;
}

// ---------------- fused dual GEMM: out = relu(mean @ WlT + x @ WrT + b) ----------------
// block: 256 threads, tile 64 rows x 128 cols; thread: 4 rows x 8 cols
__global__ __launch_bounds__(256) void gemm_fused_kernel(
    const float* __restrict__ xin, const float* __restrict__ mean,
    const float* __restrict__ WlT, const float* __restrict__ bias,
    const float* __restrict__ WrT, float* __restrict__ xout)
{
    __shared__ float sA[64][132];  // +4 pad keeps 16B alignment & kills bank conflicts
    const int tid = threadIdx.x;
    const int tx = tid & 15;       // column group: j0 = tx*8
    const int ty = tid >> 4;       // row group:    r0 = ty*4
    const int row0 = blockIdx.x * 64;
    const int j0 = tx * 8;

    float acc[4][8];
#pragma unroll
    for (int r = 0; r < 4; r++)
#pragma unroll
        for (int j = 0; j < 8; j++) acc[r][j] = 0.0f;

    for (int pass = 0; pass < 2; pass++) {
        const float* src = pass ? xin : mean;
        const float* WT  = pass ? WrT : WlT;
        __syncthreads();
        for (int idx = tid; idx < 64 * HID; idx += 256) {
            int r = idx >> 7, c = idx & 127;
            int gr = row0 + r;
            sA[r][c] = (gr < N_NODES) ? src[(size_t)gr * HID + c] : 0.0f;
        }
        __syncthreads();

        for (int k = 0; k < HID; k += 4) {
            float a[4][4];
#pragma unroll
            for (int r = 0; r < 4; r++) {
                float4 t = *(const float4*)&sA[ty * 4 + r][k];
                a[r][0] = t.x; a[r][1] = t.y; a[r][2] = t.z; a[r][3] = t.w;
            }
#pragma unroll
            for (int kk = 0; kk < 4; kk++) {
                float4 w0 = *(const float4*)(WT + (k + kk) * HID + j0);
                float4 w1 = *(const float4*)(WT + (k + kk) * HID + j0 + 4);
#pragma unroll
                for (int r = 0; r < 4; r++) {
                    float av = a[r][kk];
                    acc[r][0] += av * w0.x; acc[r][1] += av * w0.y;
                    acc[r][2] += av * w0.z; acc[r][3] += av * w0.w;
                    acc[r][4] += av * w1.x; acc[r][5] += av * w1.y;
                    acc[r][6] += av * w1.z; acc[r][7] += av * w1.w;
                }
            }
        }
    }

#pragma unroll
    for (int r = 0; r < 4; r++) {
        int gr = row0 + ty * 4 + r;
        if (gr < N_NODES) {
#pragma unroll
            for (int jj = 0; jj < 8; jj++) {
                float v = acc[r][jj] + bias[j0 + jj];
                xout[(size_t)gr * HID + j0 + jj] = fmaxf(v, 0.0f);
            }
        }
    }
}

// ---------------- global add pool: warp per node ----------------
__global__ void pool_kernel(const float* __restrict__ x, const int* __restrict__ batch,
                            float* __restrict__ pool) {
    int w = (blockIdx.x * blockDim.x + threadIdx.x) >> 5;
    int lane = threadIdx.x & 31;
    if (w >= N_NODES) return;
    int gph = batch[w];
    float4 v = *(const float4*)(x + (size_t)w * HID + lane * 4);
    float* p = pool + (size_t)gph * HID + lane * 4;
    atomicAdd(p + 0, v.x);
    atomicAdd(p + 1, v.y);
    atomicAdd(p + 2, v.z);
    atomicAdd(p + 3, v.w);
}

// ---------------- MLP head + log_softmax: block per graph ----------------
__global__ void mlp_kernel(const float* __restrict__ pool,
                           const float* __restrict__ W1, const float* __restrict__ b1,
                           const float* __restrict__ W2, const float* __restrict__ b2,
                           float* __restrict__ out) {
    __shared__ float sg[HID];
    __shared__ float sh[HID];
    __shared__ float sl[N_CLASSES];
    int gph = blockIdx.x;
    int t = threadIdx.x;

    sg[t] = fmaxf(pool[(size_t)gph * HID + t], 0.0f);  // relu(g)
    __syncthreads();

    float acc = b1[t];
    const float* w1r = W1 + (size_t)t * HID;
#pragma unroll 8
    for (int k = 0; k < HID; k++) acc += sg[k] * w1r[k];
    sh[t] = fmaxf(acc, 0.0f);
    __syncthreads();

    if (t < N_CLASSES) {
        float a = b2[t];
        const float* w2r = W2 + (size_t)t * HID;
#pragma unroll 8
        for (int k = 0; k < HID; k++) a += sh[k] * w2r[k];
        sl[t] = a;
    }
    __syncthreads();

    if (t == 0) {
        float m = -1e30f;
        for (int c = 0; c < N_CLASSES; c++) m = fmaxf(m, sl[c]);
        float s = 0.0f;
        for (int c = 0; c < N_CLASSES; c++) s += expf(sl[c] - m);
        float lse = m + logf(s);
        for (int c = 0; c < N_CLASSES; c++) out[(size_t)gph * N_CLASSES + c] = sl[c] - lse;
    }
}

// ---------------- launch ----------------
extern "C" void kernel_launch(void* const* d_in, const int* in_sizes, int n_in,
                              void* d_out, int out_size) {
    const float* x     = (const float*)d_in[0];
    // d_in[1] = edge_attr (ignored by SAGEConv)
    const int*   ei    = (const int*)d_in[2];
    const int*   srcE  = ei;
    const int*   dstE  = ei + N_EDGES;
    const int*   batch = (const int*)d_in[3];
    const float* Wl    = (const float*)d_in[4];
    const float* bl    = (const float*)d_in[5];
    const float* Wr    = (const float*)d_in[6];
    const float* W1    = (const float*)d_in[7];
    const float* b1    = (const float*)d_in[8];
    const float* W2    = (const float*)d_in[9];
    const float* b2    = (const float*)d_in[10];
    float* out = (float*)d_out;

    // resolve scratch addresses (pure host queries; graph-capture safe)
    int *p_cnt, *p_row, *p_tmp, *p_csr;
    float *p_mean, *p_h0, *p_h1, *p_pool, *p_WlT, *p_WrT;
    cudaGetSymbolAddress((void**)&p_cnt, g_cnt);
    cudaGetSymbolAddress((void**)&p_row, g_row);
    cudaGetSymbolAddress((void**)&p_tmp, g_tmp);
    cudaGetSymbolAddress((void**)&p_csr, g_csr);
    cudaGetSymbolAddress((void**)&p_mean, g_mean);
    cudaGetSymbolAddress((void**)&p_h0, g_h0);
    cudaGetSymbolAddress((void**)&p_h1, g_h1);
    cudaGetSymbolAddress((void**)&p_pool, g_pool);
    cudaGetSymbolAddress((void**)&p_WlT, g_WlT);
    cudaGetSymbolAddress((void**)&p_WrT, g_WrT);

    const int TB = 256;
    const int edge_blocks = (N_EDGES + TB - 1) / TB;
    const int node_blocks = (N_NODES + TB - 1) / TB;
    const int warp_node_blocks = (N_NODES * 32 + TB - 1) / TB;  // warp per node
    const int gemm_blocks = (N_NODES + 63) / 64;

    // CSR build (once per launch, reused by all 3 layers)
    zero_int_kernel<<<node_blocks, TB>>>(p_cnt, N_NODES);
    zero_float_kernel<<<(N_GRAPHS * HID + TB - 1) / TB, TB>>>(p_pool, N_GRAPHS * HID);
    count_kernel<<<edge_blocks, TB>>>(dstE, p_cnt, N_EDGES);
    scan_kernel<<<1, 1024>>>(p_cnt, p_row);
    copy_int_kernel<<<node_blocks, TB>>>(p_row, p_tmp, N_NODES);
    fill_csr_kernel<<<edge_blocks, TB>>>(srcE, dstE, p_tmp, p_csr, N_EDGES);

    // pre-transpose weights for coalesced GEMM reads
    transpose_w_kernel<<<(N_LAYERS * HID * HID + TB - 1) / TB, TB>>>(Wl, Wr, p_WlT, p_WrT);

    const float* cur = x;
    float* bufs[2] = {p_h0, p_h1};
    for (int l = 0; l < N_LAYERS; l++) {
        aggregate_kernel<<<warp_node_blocks, TB>>>(cur, p_mean);
        gemm_fused_kernel<<<gemm_blocks, TB>>>(
            cur, p_mean,
            p_WlT + l * HID * HID, bl + l * HID, p_WrT + l * HID * HID,
            bufs[l & 1]);
        cur = bufs[l & 1];
    }

    pool_kernel<<<warp_node_blocks, TB>>>(cur, batch, p_pool);
    mlp_kernel<<<N_GRAPHS, HID>>>(p_pool, W1, b1, W2, b2, out);
}

// round 3
// speedup vs baseline: 1.2398x; 1.2398x over previous
#include <cuda_runtime.h>
#include <math.h>

#define N_NODES 50000
#define N_EDGES 600000
#define N_GRAPHS 500
#define HID 128
#define N_LAYERS 3
#define N_CLASSES 10

#define SCAN_B 512
#define SCAN_NB ((N_NODES + SCAN_B - 1) / SCAN_B)   // 98

// ---------------- scratch (device globals; no allocs allowed) ----------------
__device__ int   g_cnt[N_NODES];
__device__ int   g_row[N_NODES + 1];
__device__ int   g_tmp[N_NODES];
__device__ int   g_csr[N_EDGES];
__device__ int   g_bsum[SCAN_NB];
__device__ int   g_boff[SCAN_NB];
__device__ float g_mean[(size_t)N_NODES * HID];
__device__ float g_h0[(size_t)N_NODES * HID];
__device__ float g_h1[(size_t)N_NODES * HID];
__device__ float g_pool[N_GRAPHS * HID];
__device__ float g_WlT[N_LAYERS * HID * HID];
__device__ float g_WrT[N_LAYERS * HID * HID];

// ---------------- f32x2 packed math helpers ----------------
__device__ __forceinline__ unsigned long long fma2(unsigned long long a,
                                                   unsigned long long b,
                                                   unsigned long long c) {
    unsigned long long d;
    asm("fma.rn.f32x2 %0, %1, %2, %3;" : "=l"(d) : "l"(a), "l"(b), "l"(c));
    return d;
}
__device__ __forceinline__ unsigned long long pack2(float v) {
    unsigned long long d;
    asm("mov.b64 %0, {%1, %1};" : "=l"(d) : "f"(v));
    return d;
}
__device__ __forceinline__ float2 unpack2(unsigned long long v) {
    float2 r;
    asm("mov.b64 {%0, %1}, %2;" : "=f"(r.x), "=f"(r.y) : "l"(v));
    return r;
}

// ---------------- tiny utility kernels ----------------
__global__ void zero_int_kernel(int* p, int n) {
    int i = blockIdx.x * blockDim.x + threadIdx.x;
    if (i < n) p[i] = 0;
}

__global__ void count_kernel(const int* __restrict__ dst, int* __restrict__ cnt, int nE) {
    int i = blockIdx.x * blockDim.x + threadIdx.x;
    if (i < nE) atomicAdd(&cnt[dst[i]], 1);
}

// ---------------- hierarchical exclusive scan over counts ----------------
__global__ void scan_partial_kernel(const int* __restrict__ cnt, int* __restrict__ bsum) {
    __shared__ int sh[SCAN_B];
    int t = threadIdx.x;
    int i = blockIdx.x * SCAN_B + t;
    sh[t] = (i < N_NODES) ? cnt[i] : 0;
    __syncthreads();
#pragma unroll
    for (int off = SCAN_B / 2; off > 0; off >>= 1) {
        if (t < off) sh[t] += sh[t + off];
        __syncthreads();
    }
    if (t == 0) bsum[blockIdx.x] = sh[0];
}

__global__ void scan_bsum_kernel(const int* __restrict__ bsum, int* __restrict__ boff) {
    __shared__ int sh[128];
    int t = threadIdx.x;
    int v = (t < SCAN_NB) ? bsum[t] : 0;
    sh[t] = v;
    __syncthreads();
#pragma unroll
    for (int off = 1; off < 128; off <<= 1) {
        int add = (t >= off) ? sh[t - off] : 0;
        __syncthreads();
        sh[t] += add;
        __syncthreads();
    }
    if (t < SCAN_NB) boff[t] = sh[t] - v;   // exclusive
}

__global__ void scan_apply_kernel(const int* __restrict__ cnt, const int* __restrict__ boff,
                                  int* __restrict__ row, int* __restrict__ tmp) {
    __shared__ int sh[SCAN_B];
    int t = threadIdx.x;
    int i = blockIdx.x * SCAN_B + t;
    int v = (i < N_NODES) ? cnt[i] : 0;
    sh[t] = v;
    __syncthreads();
#pragma unroll
    for (int off = 1; off < SCAN_B; off <<= 1) {
        int add = (t >= off) ? sh[t - off] : 0;
        __syncthreads();
        sh[t] += add;
        __syncthreads();
    }
    int excl = boff[blockIdx.x] + sh[t] - v;
    if (i < N_NODES) { row[i] = excl; tmp[i] = excl; }
    if (i == N_NODES - 1) row[N_NODES] = excl + v;
}

__global__ void fill_csr_kernel(const int* __restrict__ src, const int* __restrict__ dst,
                                int* __restrict__ tmp, int* __restrict__ csr, int nE) {
    int i = blockIdx.x * blockDim.x + threadIdx.x;
    if (i < nE) {
        int p = atomicAdd(&tmp[dst[i]], 1);
        csr[p] = src[i];
    }
}

// transpose Wl/Wr (3 layers each, 128x128): WT[k][j] = W[j][k]
__global__ void transpose_w_kernel(const float* __restrict__ Wl, const float* __restrict__ Wr,
                                   float* __restrict__ WlT, float* __restrict__ WrT) {
    int i = blockIdx.x * blockDim.x + threadIdx.x;
    if (i >= N_LAYERS * HID * HID) return;
    int l = i >> 14;
    int j = (i >> 7) & 127;
    int k = i & 127;
    int o = (l << 14) + (k << 7) + j;
    WlT[o] = Wl[i];
    WrT[o] = Wr[i];
}

// ---------------- mean aggregation: warp per node, CSR gather ----------------
__global__ void aggregate_kernel(const float* __restrict__ x, float* __restrict__ mean) {
    int w = (blockIdx.x * blockDim.x + threadIdx.x) >> 5;
    int lane = threadIdx.x & 31;
    if (w >= N_NODES) return;
    int beg = g_row[w];
    int end = g_row[w + 1];
    float4 s = make_float4(0.f, 0.f, 0.f, 0.f);
    for (int i = beg; i < end; i++) {
        int sn = g_csr[i];
        float4 v = *(const float4*)(x + (size_t)sn * HID + lane * 4);
        s.x += v.x; s.y += v.y; s.z += v.z; s.w += v.w;
    }
    float ic = 1.0f / fmaxf((float)(end - beg), 1.0f);
    s.x *= ic; s.y *= ic; s.z *= ic; s.w *= ic;
    *(float4*)(mean + (size_t)w * HID + lane * 4) = s;
}

// ---------------- fused dual GEMM (f32x2): out = relu(mean@WlT + x@WrT + b) ----
// block: 256 threads, tile 128 rows x 128 cols; thread: 8 rows x 8 cols (4 f32x2 pairs)
#define SA_STRIDE 132
__global__ __launch_bounds__(256) void gemm_fused_kernel(
    const float* __restrict__ xin, const float* __restrict__ mean,
    const float* __restrict__ WlT, const float* __restrict__ bias,
    const float* __restrict__ WrT, float* __restrict__ xout)
{
    extern __shared__ float sA[];   // [128][SA_STRIDE]
    const int tid = threadIdx.x;
    const int tx = tid & 15;        // 16 col groups of 8
    const int ty = tid >> 4;        // 16 row groups of 8
    const int row0 = blockIdx.x * 128;
    const int j0 = tx * 8;
    const int r0 = ty * 8;

    unsigned long long acc[8][4];
#pragma unroll
    for (int r = 0; r < 8; r++)
#pragma unroll
        for (int p = 0; p < 4; p++) acc[r][p] = 0ull;

    for (int pass = 0; pass < 2; pass++) {
        const float* src = pass ? xin : mean;
        const float* WT  = pass ? WrT : WlT;
        __syncthreads();
        // stage 128x128 A tile (float4 per thread x16)
        for (int idx = tid; idx < 128 * 32; idx += 256) {
            int r = idx >> 5;
            int c = (idx & 31) << 2;
            int gr = row0 + r;
            float4 v = make_float4(0.f, 0.f, 0.f, 0.f);
            if (gr < N_NODES) v = *(const float4*)(src + (size_t)gr * HID + c);
            *(float4*)&sA[r * SA_STRIDE + c] = v;
        }
        __syncthreads();

        for (int k = 0; k < HID; k += 4) {
            float a[8][4];
#pragma unroll
            for (int r = 0; r < 8; r++) {
                float4 t = *(const float4*)&sA[(r0 + r) * SA_STRIDE + k];
                a[r][0] = t.x; a[r][1] = t.y; a[r][2] = t.z; a[r][3] = t.w;
            }
#pragma unroll
            for (int kk = 0; kk < 4; kk++) {
                ulonglong2 w01 = *(const ulonglong2*)(WT + (size_t)(k + kk) * HID + j0);
                ulonglong2 w23 = *(const ulonglong2*)(WT + (size_t)(k + kk) * HID + j0 + 4);
#pragma unroll
                for (int r = 0; r < 8; r++) {
                    unsigned long long av2 = pack2(a[r][kk]);
                    acc[r][0] = fma2(av2, w01.x, acc[r][0]);
                    acc[r][1] = fma2(av2, w01.y, acc[r][1]);
                    acc[r][2] = fma2(av2, w23.x, acc[r][2]);
                    acc[r][3] = fma2(av2, w23.y, acc[r][3]);
                }
            }
        }
    }

    float4 b0 = *(const float4*)(bias + j0);
    float4 b1 = *(const float4*)(bias + j0 + 4);
    float bb[8] = {b0.x, b0.y, b0.z, b0.w, b1.x, b1.y, b1.z, b1.w};
#pragma unroll
    for (int r = 0; r < 8; r++) {
        int gr = row0 + r0 + r;
        if (gr < N_NODES) {
            float o[8];
#pragma unroll
            for (int p = 0; p < 4; p++) {
                float2 v = unpack2(acc[r][p]);
                o[2 * p]     = fmaxf(v.x + bb[2 * p], 0.0f);
                o[2 * p + 1] = fmaxf(v.y + bb[2 * p + 1], 0.0f);
            }
            float* dstp = xout + (size_t)gr * HID + j0;
            *(float4*)(dstp)     = make_float4(o[0], o[1], o[2], o[3]);
            *(float4*)(dstp + 4) = make_float4(o[4], o[5], o[6], o[7]);
        }
    }
}

// ---------------- global add pool: block per graph (batch is SORTED) --------
__global__ void pool_kernel(const float* __restrict__ x, const int* __restrict__ batch,
                            float* __restrict__ pool) {
    __shared__ int s_beg, s_end;
    int g = blockIdx.x;
    int t = threadIdx.x;
    if (t == 0) {
        // lower_bound(batch, g)
        int lo = 0, hi = N_NODES;
        while (lo < hi) { int m = (lo + hi) >> 1; if (batch[m] < g) lo = m + 1; else hi = m; }
        s_beg = lo;
    }
    if (t == 1) {
        // lower_bound(batch, g+1)
        int lo = 0, hi = N_NODES;
        while (lo < hi) { int m = (lo + hi) >> 1; if (batch[m] < g + 1) lo = m + 1; else hi = m; }
        s_end = lo;
    }
    __syncthreads();
    int beg = s_beg, end = s_end;
    float s = 0.0f;
    for (int n = beg; n < end; n++) s += x[(size_t)n * HID + t];
    pool[(size_t)g * HID + t] = s;
}

// ---------------- MLP head + log_softmax: block per graph ----------------
__global__ void mlp_kernel(const float* __restrict__ pool,
                           const float* __restrict__ W1, const float* __restrict__ b1,
                           const float* __restrict__ W2, const float* __restrict__ b2,
                           float* __restrict__ out) {
    __shared__ float sg[HID];
    __shared__ float sh[HID];
    __shared__ float sl[N_CLASSES];
    int gph = blockIdx.x;
    int t = threadIdx.x;

    sg[t] = fmaxf(pool[(size_t)gph * HID + t], 0.0f);  // relu(g)
    __syncthreads();

    float acc = b1[t];
    const float* w1r = W1 + (size_t)t * HID;
#pragma unroll 8
    for (int k = 0; k < HID; k++) acc += sg[k] * w1r[k];
    sh[t] = fmaxf(acc, 0.0f);
    __syncthreads();

    if (t < N_CLASSES) {
        float a = b2[t];
        const float* w2r = W2 + (size_t)t * HID;
#pragma unroll 8
        for (int k = 0; k < HID; k++) a += sh[k] * w2r[k];
        sl[t] = a;
    }
    __syncthreads();

    if (t == 0) {
        float m = -1e30f;
        for (int c = 0; c < N_CLASSES; c++) m = fmaxf(m, sl[c]);
        float s = 0.0f;
        for (int c = 0; c < N_CLASSES; c++) s += expf(sl[c] - m);
        float lse = m + logf(s);
        for (int c = 0; c < N_CLASSES; c++) out[(size_t)gph * N_CLASSES + c] = sl[c] - lse;
    }
}

// ---------------- launch ----------------
extern "C" void kernel_launch(void* const* d_in, const int* in_sizes, int n_in,
                              void* d_out, int out_size) {
    const float* x     = (const float*)d_in[0];
    // d_in[1] = edge_attr (ignored by SAGEConv)
    const int*   ei    = (const int*)d_in[2];
    const int*   srcE  = ei;
    const int*   dstE  = ei + N_EDGES;
    const int*   batch = (const int*)d_in[3];
    const float* Wl    = (const float*)d_in[4];
    const float* bl    = (const float*)d_in[5];
    const float* Wr    = (const float*)d_in[6];
    const float* W1    = (const float*)d_in[7];
    const float* b1    = (const float*)d_in[8];
    const float* W2    = (const float*)d_in[9];
    const float* b2    = (const float*)d_in[10];
    float* out = (float*)d_out;

    int *p_cnt, *p_row, *p_tmp, *p_csr, *p_bsum, *p_boff;
    float *p_mean, *p_h0, *p_h1, *p_pool, *p_WlT, *p_WrT;
    cudaGetSymbolAddress((void**)&p_cnt, g_cnt);
    cudaGetSymbolAddress((void**)&p_row, g_row);
    cudaGetSymbolAddress((void**)&p_tmp, g_tmp);
    cudaGetSymbolAddress((void**)&p_csr, g_csr);
    cudaGetSymbolAddress((void**)&p_bsum, g_bsum);
    cudaGetSymbolAddress((void**)&p_boff, g_boff);
    cudaGetSymbolAddress((void**)&p_mean, g_mean);
    cudaGetSymbolAddress((void**)&p_h0, g_h0);
    cudaGetSymbolAddress((void**)&p_h1, g_h1);
    cudaGetSymbolAddress((void**)&p_pool, g_pool);
    cudaGetSymbolAddress((void**)&p_WlT, g_WlT);
    cudaGetSymbolAddress((void**)&p_WrT, g_WrT);

    static int smem_set = 0;
    const int GEMM_SMEM = 128 * SA_STRIDE * 4;   // 67584 B
    if (!smem_set) {
        cudaFuncSetAttribute(gemm_fused_kernel,
                             cudaFuncAttributeMaxDynamicSharedMemorySize, GEMM_SMEM);
        smem_set = 1;
    }

    const int TB = 256;
    const int edge_blocks = (N_EDGES + TB - 1) / TB;
    const int node_blocks = (N_NODES + TB - 1) / TB;
    const int warp_node_blocks = (N_NODES * 32 + TB - 1) / TB;
    const int gemm_blocks = (N_NODES + 127) / 128;

    // CSR build (reused by all 3 layers)
    zero_int_kernel<<<node_blocks, TB>>>(p_cnt, N_NODES);
    count_kernel<<<edge_blocks, TB>>>(dstE, p_cnt, N_EDGES);
    scan_partial_kernel<<<SCAN_NB, SCAN_B>>>(p_cnt, p_bsum);
    scan_bsum_kernel<<<1, 128>>>(p_bsum, p_boff);
    scan_apply_kernel<<<SCAN_NB, SCAN_B>>>(p_cnt, p_boff, p_row, p_tmp);
    fill_csr_kernel<<<edge_blocks, TB>>>(srcE, dstE, p_tmp, p_csr, N_EDGES);

    transpose_w_kernel<<<(N_LAYERS * HID * HID + TB - 1) / TB, TB>>>(Wl, Wr, p_WlT, p_WrT);

    const float* cur = x;
    float* bufs[2] = {p_h0, p_h1};
    for (int l = 0; l < N_LAYERS; l++) {
        aggregate_kernel<<<warp_node_blocks, TB>>>(cur, p_mean);
        gemm_fused_kernel<<<gemm_blocks, TB, GEMM_SMEM>>>(
            cur, p_mean,
            p_WlT + l * HID * HID, bl + l * HID, p_WrT + l * HID * HID,
            bufs[l & 1]);
        cur = bufs[l & 1];
    }

    pool_kernel<<<N_GRAPHS, HID>>>(cur, batch, p_pool);
    mlp_kernel<<<N_GRAPHS, HID>>>(p_pool, W1, b1, W2, b2, out);
}

// round 7
// speedup vs baseline: 2.1654x; 1.7465x over previous
#include <cuda_runtime.h>
#include <cuda_bf16.h>
#include <mma.h>
#include <math.h>
#include <stdint.h>

using namespace nvcuda;

#define N_NODES 50000
#define N_EDGES 600000
#define N_GRAPHS 500
#define HID 128
#define N_LAYERS 3
#define N_CLASSES 10

#define SCAN_B 512
#define SCAN_NB ((N_NODES + SCAN_B - 1) / SCAN_B)   // 98

// ---------------- scratch (device globals; no allocs allowed) ----------------
__device__ int   g_cnt[N_NODES];
__device__ int   g_row[N_NODES + 1];
__device__ int   g_tmp[N_NODES];
__device__ int   g_csr[N_EDGES];
__device__ int   g_bsum[SCAN_NB];
__device__ int   g_boff[SCAN_NB];
__device__ float g_mean[(size_t)N_NODES * HID];
__device__ float g_h0[(size_t)N_NODES * HID];
__device__ float g_h1[(size_t)N_NODES * HID];
__device__ float g_pool[N_GRAPHS * HID];

// ---------------- tiny utility kernels ----------------
__global__ void zero_int_kernel(int* p, int n) {
    int i = blockIdx.x * blockDim.x + threadIdx.x;
    if (i < n) p[i] = 0;
}

__global__ void count_kernel(const int* __restrict__ dst, int* __restrict__ cnt, int nE) {
    int i = blockIdx.x * blockDim.x + threadIdx.x;
    if (i < nE) atomicAdd(&cnt[dst[i]], 1);
}

__global__ void scan_partial_kernel(const int* __restrict__ cnt, int* __restrict__ bsum) {
    __shared__ int sh[SCAN_B];
    int t = threadIdx.x;
    int i = blockIdx.x * SCAN_B + t;
    sh[t] = (i < N_NODES) ? cnt[i] : 0;
    __syncthreads();
#pragma unroll
    for (int off = SCAN_B / 2; off > 0; off >>= 1) {
        if (t < off) sh[t] += sh[t + off];
        __syncthreads();
    }
    if (t == 0) bsum[blockIdx.x] = sh[0];
}

__global__ void scan_bsum_kernel(const int* __restrict__ bsum, int* __restrict__ boff) {
    __shared__ int sh[128];
    int t = threadIdx.x;
    int v = (t < SCAN_NB) ? bsum[t] : 0;
    sh[t] = v;
    __syncthreads();
#pragma unroll
    for (int off = 1; off < 128; off <<= 1) {
        int add = (t >= off) ? sh[t - off] : 0;
        __syncthreads();
        sh[t] += add;
        __syncthreads();
    }
    if (t < SCAN_NB) boff[t] = sh[t] - v;
}

__global__ void scan_apply_kernel(const int* __restrict__ cnt, const int* __restrict__ boff,
                                  int* __restrict__ row, int* __restrict__ tmp) {
    __shared__ int sh[SCAN_B];
    int t = threadIdx.x;
    int i = blockIdx.x * SCAN_B + t;
    int v = (i < N_NODES) ? cnt[i] : 0;
    sh[t] = v;
    __syncthreads();
#pragma unroll
    for (int off = 1; off < SCAN_B; off <<= 1) {
        int add = (t >= off) ? sh[t - off] : 0;
        __syncthreads();
        sh[t] += add;
        __syncthreads();
    }
    int excl = boff[blockIdx.x] + sh[t] - v;
    if (i < N_NODES) { row[i] = excl; tmp[i] = excl; }
    if (i == N_NODES - 1) row[N_NODES] = excl + v;
}

__global__ void fill_csr_kernel(const int* __restrict__ src, const int* __restrict__ dst,
                                int* __restrict__ tmp, int* __restrict__ csr, int nE) {
    int i = blockIdx.x * blockDim.x + threadIdx.x;
    if (i < nE) {
        int p = atomicAdd(&tmp[dst[i]], 1);
        csr[p] = src[i];
    }
}

// ---------------- mean aggregation: warp per node, CSR gather ----------------
__global__ void aggregate_kernel(const float* __restrict__ x, float* __restrict__ mean) {
    int w = (blockIdx.x * blockDim.x + threadIdx.x) >> 5;
    int lane = threadIdx.x & 31;
    if (w >= N_NODES) return;
    int beg = g_row[w];
    int end = g_row[w + 1];
    float4 s = make_float4(0.f, 0.f, 0.f, 0.f);
    for (int i = beg; i < end; i++) {
        int sn = g_csr[i];
        float4 v = *(const float4*)(x + (size_t)sn * HID + lane * 4);
        s.x += v.x; s.y += v.y; s.z += v.z; s.w += v.w;
    }
    float ic = 1.0f / fmaxf((float)(end - beg), 1.0f);
    s.x *= ic; s.y *= ic; s.z *= ic; s.w *= ic;
    *(float4*)(mean + (size_t)w * HID + lane * 4) = s;
}

// ---------------- wmma (HMMA) fused dual GEMM, bf16x3 emulation -------------
// out = relu(mean @ Wl^T + x @ Wr^T + b), fp32 accumulators.
// Block: 256 threads (8 warps, 4x2), tile 128x128. Per warp: 32 rows x 64 cols.
// D ~= Ah*Bh + Ah*Bl + Al*Bh, where a = ah + al (bf16 split).
#define LDA 136                         // bf16 stride, pad 8 halves (16B)
#define LDC 132                         // fp32 epilogue stride
#define SM_AH 0
#define SM_AL (128 * LDA)
#define SM_BH (2 * 128 * LDA)
#define SM_BL (3 * 128 * LDA)
#define GEMM_SMEM (4 * 128 * LDA * 2)   // 139264 B (bf16)

__global__ __launch_bounds__(256) void gemm_wmma_kernel(
    const float* __restrict__ xin, const float* __restrict__ mean,
    const float* __restrict__ Wl, const float* __restrict__ Wr,
    const float* __restrict__ bias, float* __restrict__ xout)
{
    extern __shared__ __nv_bfloat16 sm[];
    const int tid = threadIdx.x;
    const int wid = tid >> 5;
    const int wr = wid >> 1;            // warp row group (0..3): rows wr*32
    const int wc = wid & 1;             // warp col group (0..1): cols wc*64
    const int row0 = blockIdx.x * 128;

    wmma::fragment<wmma::accumulator, 16, 16, 16, float> acc[2][4];
#pragma unroll
    for (int i = 0; i < 2; i++)
#pragma unroll
        for (int j = 0; j < 4; j++) wmma::fill_fragment(acc[i][j], 0.0f);

    for (int side = 0; side < 2; side++) {
        const float* A = side ? xin : mean;
        const float* W = side ? Wr : Wl;
        __syncthreads();   // all warps done reading previous side's tiles

        // stage A: 128 rows x 128 cols fp32 -> bf16 hi/lo
        for (int i = tid; i < 128 * 32; i += 256) {
            int r = i >> 5;
            int c = (i & 31) << 2;
            int gr = row0 + r;
            float4 v = make_float4(0.f, 0.f, 0.f, 0.f);
            if (gr < N_NODES) v = *(const float4*)(A + (size_t)gr * HID + c);
            __nv_bfloat162 h0 = __floats2bfloat162_rn(v.x, v.y);
            __nv_bfloat162 h1 = __floats2bfloat162_rn(v.z, v.w);
            float2 f0 = __bfloat1622float2(h0);
            float2 f1 = __bfloat1622float2(h1);
            __nv_bfloat162 l0 = __floats2bfloat162_rn(v.x - f0.x, v.y - f0.y);
            __nv_bfloat162 l1 = __floats2bfloat162_rn(v.z - f1.x, v.w - f1.y);
            *(__nv_bfloat162*)&sm[SM_AH + r * LDA + c]     = h0;
            *(__nv_bfloat162*)&sm[SM_AH + r * LDA + c + 2] = h1;
            *(__nv_bfloat162*)&sm[SM_AL + r * LDA + c]     = l0;
            *(__nv_bfloat162*)&sm[SM_AL + r * LDA + c + 2] = l1;
        }
        // stage W: [j][k] row-major fp32 -> bf16 hi/lo (used as col_major B)
        for (int i = tid; i < 128 * 32; i += 256) {
            int j = i >> 5;
            int k = (i & 31) << 2;
            float4 v = *(const float4*)(W + (size_t)j * HID + k);
            __nv_bfloat162 h0 = __floats2bfloat162_rn(v.x, v.y);
            __nv_bfloat162 h1 = __floats2bfloat162_rn(v.z, v.w);
            float2 f0 = __bfloat1622float2(h0);
            float2 f1 = __bfloat1622float2(h1);
            __nv_bfloat162 l0 = __floats2bfloat162_rn(v.x - f0.x, v.y - f0.y);
            __nv_bfloat162 l1 = __floats2bfloat162_rn(v.z - f1.x, v.w - f1.y);
            *(__nv_bfloat162*)&sm[SM_BH + j * LDA + k]     = h0;
            *(__nv_bfloat162*)&sm[SM_BH + j * LDA + k + 2] = h1;
            *(__nv_bfloat162*)&sm[SM_BL + j * LDA + k]     = l0;
            *(__nv_bfloat162*)&sm[SM_BL + j * LDA + k + 2] = l1;
        }
        __syncthreads();

        for (int k = 0; k < HID; k += 16) {
            wmma::fragment<wmma::matrix_a, 16, 16, 16, __nv_bfloat16, wmma::row_major> ah[2], al[2];
            wmma::fragment<wmma::matrix_b, 16, 16, 16, __nv_bfloat16, wmma::col_major> bh[4], bl[4];
#pragma unroll
            for (int i = 0; i < 2; i++) {
                int r = wr * 32 + i * 16;
                wmma::load_matrix_sync(ah[i], &sm[SM_AH + r * LDA + k], LDA);
                wmma::load_matrix_sync(al[i], &sm[SM_AL + r * LDA + k], LDA);
            }
#pragma unroll
            for (int j = 0; j < 4; j++) {
                int cj = wc * 64 + j * 16;
                wmma::load_matrix_sync(bh[j], &sm[SM_BH + cj * LDA + k], LDA);
                wmma::load_matrix_sync(bl[j], &sm[SM_BL + cj * LDA + k], LDA);
            }
#pragma unroll
            for (int i = 0; i < 2; i++)
#pragma unroll
                for (int j = 0; j < 4; j++) {
                    wmma::mma_sync(acc[i][j], ah[i], bh[j], acc[i][j]);
                    wmma::mma_sync(acc[i][j], ah[i], bl[j], acc[i][j]);
                    wmma::mma_sync(acc[i][j], al[i], bh[j], acc[i][j]);
                }
        }
    }

    // epilogue: stage C in smem (reuse), then bias + relu + store
    __syncthreads();
    float* Csm = (float*)sm;
#pragma unroll
    for (int i = 0; i < 2; i++)
#pragma unroll
        for (int j = 0; j < 4; j++) {
            int r = wr * 32 + i * 16;
            int c = wc * 64 + j * 16;
            wmma::store_matrix_sync(&Csm[r * LDC + c], acc[i][j], LDC, wmma::mem_row_major);
        }
    __syncthreads();

    for (int i = tid; i < 128 * 32; i += 256) {
        int r = i >> 5;
        int c = (i & 31) << 2;
        int gr = row0 + r;
        if (gr < N_NODES) {
            float4 v = *(const float4*)&Csm[r * LDC + c];
            float4 bv = *(const float4*)(bias + c);
            float4 o;
            o.x = fmaxf(v.x + bv.x, 0.f);
            o.y = fmaxf(v.y + bv.y, 0.f);
            o.z = fmaxf(v.z + bv.z, 0.f);
            o.w = fmaxf(v.w + bv.w, 0.f);
            *(float4*)(xout + (size_t)gr * HID + c) = o;
        }
    }
}

// ---------------- global add pool: block per graph (batch is SORTED) --------
__global__ void pool_kernel(const float* __restrict__ x, const int* __restrict__ batch,
                            float* __restrict__ pool) {
    __shared__ int s_beg, s_end;
    int g = blockIdx.x;
    int t = threadIdx.x;
    if (t == 0) {
        int lo = 0, hi = N_NODES;
        while (lo < hi) { int m = (lo + hi) >> 1; if (batch[m] < g) lo = m + 1; else hi = m; }
        s_beg = lo;
    }
    if (t == 1) {
        int lo = 0, hi = N_NODES;
        while (lo < hi) { int m = (lo + hi) >> 1; if (batch[m] < g + 1) lo = m + 1; else hi = m; }
        s_end = lo;
    }
    __syncthreads();
    int beg = s_beg, end = s_end;
    float s = 0.0f;
    for (int n = beg; n < end; n++) s += x[(size_t)n * HID + t];
    pool[(size_t)g * HID + t] = s;
}

// ---------------- MLP head + log_softmax: block per graph ----------------
__global__ void mlp_kernel(const float* __restrict__ pool,
                           const float* __restrict__ W1, const float* __restrict__ b1,
                           const float* __restrict__ W2, const float* __restrict__ b2,
                           float* __restrict__ out) {
    __shared__ float sg[HID];
    __shared__ float sh[HID];
    __shared__ float sl[N_CLASSES];
    int gph = blockIdx.x;
    int t = threadIdx.x;

    sg[t] = fmaxf(pool[(size_t)gph * HID + t], 0.0f);
    __syncthreads();

    float acc = b1[t];
    const float* w1r = W1 + (size_t)t * HID;
#pragma unroll 8
    for (int k = 0; k < HID; k++) acc += sg[k] * w1r[k];
    sh[t] = fmaxf(acc, 0.0f);
    __syncthreads();

    if (t < N_CLASSES) {
        float a = b2[t];
        const float* w2r = W2 + (size_t)t * HID;
#pragma unroll 8
        for (int k = 0; k < HID; k++) a += sh[k] * w2r[k];
        sl[t] = a;
    }
    __syncthreads();

    if (t == 0) {
        float m = -1e30f;
        for (int c = 0; c < N_CLASSES; c++) m = fmaxf(m, sl[c]);
        float s = 0.0f;
        for (int c = 0; c < N_CLASSES; c++) s += expf(sl[c] - m);
        float lse = m + logf(s);
        for (int c = 0; c < N_CLASSES; c++) out[(size_t)gph * N_CLASSES + c] = sl[c] - lse;
    }
}

// ---------------- launch ----------------
extern "C" void kernel_launch(void* const* d_in, const int* in_sizes, int n_in,
                              void* d_out, int out_size) {
    const float* x     = (const float*)d_in[0];
    // d_in[1] = edge_attr (ignored by SAGEConv)
    const int*   ei    = (const int*)d_in[2];
    const int*   srcE  = ei;
    const int*   dstE  = ei + N_EDGES;
    const int*   batch = (const int*)d_in[3];
    const float* Wl    = (const float*)d_in[4];
    const float* bl    = (const float*)d_in[5];
    const float* Wr    = (const float*)d_in[6];
    const float* W1    = (const float*)d_in[7];
    const float* b1    = (const float*)d_in[8];
    const float* W2    = (const float*)d_in[9];
    const float* b2    = (const float*)d_in[10];
    float* out = (float*)d_out;

    int *p_cnt, *p_row, *p_tmp, *p_csr, *p_bsum, *p_boff;
    float *p_mean, *p_h0, *p_h1, *p_pool;
    cudaGetSymbolAddress((void**)&p_cnt, g_cnt);
    cudaGetSymbolAddress((void**)&p_row, g_row);
    cudaGetSymbolAddress((void**)&p_tmp, g_tmp);
    cudaGetSymbolAddress((void**)&p_csr, g_csr);
    cudaGetSymbolAddress((void**)&p_bsum, g_bsum);
    cudaGetSymbolAddress((void**)&p_boff, g_boff);
    cudaGetSymbolAddress((void**)&p_mean, g_mean);
    cudaGetSymbolAddress((void**)&p_h0, g_h0);
    cudaGetSymbolAddress((void**)&p_h1, g_h1);
    cudaGetSymbolAddress((void**)&p_pool, g_pool);

    static int smem_set = 0;
    if (!smem_set) {
        cudaFuncSetAttribute(gemm_wmma_kernel,
                             cudaFuncAttributeMaxDynamicSharedMemorySize, GEMM_SMEM);
        smem_set = 1;
    }

    const int TB = 256;
    const int edge_blocks = (N_EDGES + TB - 1) / TB;
    const int node_blocks = (N_NODES + TB - 1) / TB;
    const int warp_node_blocks = (N_NODES * 32 + TB - 1) / TB;
    const int gemm_blocks = (N_NODES + 127) / 128;   // 391

    // CSR build (reused by all 3 layers)
    zero_int_kernel<<<node_blocks, TB>>>(p_cnt, N_NODES);
    count_kernel<<<edge_blocks, TB>>>(dstE, p_cnt, N_EDGES);
    scan_partial_kernel<<<SCAN_NB, SCAN_B>>>(p_cnt, p_bsum);
    scan_bsum_kernel<<<1, 128>>>(p_bsum, p_boff);
    scan_apply_kernel<<<SCAN_NB, SCAN_B>>>(p_cnt, p_boff, p_row, p_tmp);
    fill_csr_kernel<<<edge_blocks, TB>>>(srcE, dstE, p_tmp, p_csr, N_EDGES);

    const float* cur = x;
    float* bufs[2] = {p_h0, p_h1};
    for (int l = 0; l < N_LAYERS; l++) {
        aggregate_kernel<<<warp_node_blocks, TB>>>(cur, p_mean);
        gemm_wmma_kernel<<<gemm_blocks, TB, GEMM_SMEM>>>(
            cur, p_mean, Wl + (size_t)l * HID * HID, Wr + (size_t)l * HID * HID,
            bl + l * HID, bufs[l & 1]);
        cur = bufs[l & 1];
    }

    pool_kernel<<<N_GRAPHS, HID>>>(cur, batch, p_pool);
    mlp_kernel<<<N_GRAPHS, HID>>>(p_pool, W1, b1, W2, b2, out);
}